// round 9
// baseline (speedup 1.0000x reference)
#include <cuda_runtime.h>
#include <math.h>

// Problem dims (fixed by the reference)
#define Bv 32
#define Tv 128
#define Fv 64
#define Hv 64
#define BST 36           // state row stride [j][b]: conflict-free STS.128 (36 % 32 == 4)
#define WST 68           // transposed weight row stride [j][k]: conflict-free LDS.128
#define NTHREADS 512

typedef unsigned long long u64;

// ---------------------------------------------------------------------------
// Scratch (allocation-free): transposed inputs + precomputed time terms
// ---------------------------------------------------------------------------
__device__ float g_xT[Tv*Fv*Bv];   // x   -> [t][f][b]
__device__ float g_lT[Tv*Fv*Bv];   // l   -> [t][f][b]
__device__ float g_Tm[Tv*Fv*Bv];   // 1/log(t+e)
__device__ float g_sTm[Tv*Fv*Bv];  // sigmoid(Tm)
__device__ float g_fw[Tv*Bv];      // sum_f exp(-0.5*freq[b,t,f])

struct KParams { const float* p[30]; };

// ---------------------------------------------------------------------------
// Prologue: transpose + time precompute + cross-feature freq reduction
// ---------------------------------------------------------------------------
__global__ void prologue_kernel(KParams prm) {
    int b  = blockIdx.x >> 7;          // / Tv
    int t  = blockIdx.x & (Tv - 1);
    int fi = threadIdx.x;

    const float* inputs = prm.p[0];
    const float* times  = prm.p[1];
    const float* lastv  = prm.p[2];
    const float* freqs  = prm.p[3];

    int gin  = (b*Tv + t)*Fv + fi;     // [B,T,F]
    int gout = (t*Fv + fi)*Bv + b;     // [T,F,B]

    g_xT[gout] = inputs[gin];
    g_lT[gout] = lastv[gin];
    float tv = times[gin];
    float tm = 1.0f / logf(tv + 2.718281828459045f);
    g_Tm[gout]  = tm;
    g_sTm[gout] = 1.0f / (1.0f + expf(-tm));

    float e = expf(-0.5f * freqs[gin]);
    #pragma unroll
    for (int off = 16; off > 0; off >>= 1)
        e += __shfl_down_sync(0xffffffffu, e, off);
    __shared__ float red[2];
    if ((threadIdx.x & 31) == 0) red[threadIdx.x >> 5] = e;
    __syncthreads();
    if (threadIdx.x == 0) g_fw[t*Bv + b] = red[0] + red[1];
}

// ---------------------------------------------------------------------------
// Packed f32x2 helpers
// ---------------------------------------------------------------------------
__device__ __forceinline__ u64 pk2(float x) {
    u64 r; asm("mov.b64 %0, {%1, %1};" : "=l"(r) : "f"(x)); return r;
}
__device__ __forceinline__ void fma2(u64& d, u64 a, u64 b) {
    asm("fma.rn.f32x2 %0, %1, %2, %0;" : "+l"(d) : "l"(a), "l"(b));
}
__device__ __forceinline__ float2 up2(u64 v) {
    float2 r; asm("mov.b64 {%0, %1}, %2;" : "=f"(r.x), "=f"(r.y) : "l"(v)); return r;
}

// ---------------------------------------------------------------------------
// Fast-but-accurate activations (identical numerics to all prior rounds)
// ---------------------------------------------------------------------------
__device__ __forceinline__ float sigf(float x) {
    return __fdividef(1.0f, 1.0f + __expf(-x));
}
__device__ __forceinline__ float tanf_(float x) {
    float e = __expf(-2.0f * fabsf(x));
    float r = __fdividef(1.0f - e, 1.0f + e);
    return copysignf(r, x);
}
__device__ __forceinline__ float eluf(float x) {
    return x > 0.0f ? x : (__expf(x) - 1.0f);
}

// ---------------------------------------------------------------------------
// Main kernel: one CTA per (feature, direction), 512 threads (16 warps).
// Warp w: jhalf = w&1, bgroup = (w>>1)&3 (8 batches, b0=8*bgroup), mhalf = w>>3.
// Matmul split by MATRIX (not k): each matrix's full-k sum stays in one thread
//   -> bitwise-identical accumulation vs the 8-warp kernel.
//   phase1: mh=0 -> c@W_decomp, mh=1 -> h@W_d         (8 batches each)
//   phase2: mh=0 -> h2@{W_j,W_i,W_f}, mh=1 -> h2@{W_o,W_c,W_d}
// Final sums swapped via padded smem buffer; elementwise + state ownership is
// split by batch: thread handles batches bsel = b0 + mh*4 .. +3.
// ---------------------------------------------------------------------------
#define WTF   (7*Hv*WST)            // 30464 weight floats
#define STF   (3*Hv*BST)            // 6912 state floats
#define PRF   (19*Hv)               // 1216 param floats
#define REDF  (NTHREADS*7*2)        // 7168 floats (512 slots of 7 u64)
#define SMEM_FLOATS (WTF + STF + PRF + REDF)   // 45760 floats = 179 KB

__global__ __launch_bounds__(NTHREADS)
void tlstm_kernel(KParams prm, float* __restrict__ out) {
    const int f    = blockIdx.x;
    const int dir  = blockIdx.y;
    const int tid  = threadIdx.x;
    const int w    = tid >> 5;
    const int lane = tid & 31;
    const int jh   = w & 1;
    const int bg   = (w >> 1) & 3;
    const int mh   = w >> 3;
    const int b0   = bg * 8;
    const int bsel = b0 + mh * 4;            // this thread's 4 elementwise batches
    const int jcol = jh * 32 + lane;

    extern __shared__ float sm[];
    float* wT  = sm;                          // [7][Hv*WST]
    float* sH  = sm + WTF;                    // [Hv][BST]
    float* sC  = sH + Hv*BST;
    float* sH2 = sC + Hv*BST;
    float* pUV = sm + WTF + STF;              // [19][64]
    u64*   red = (u64*)(sm + WTF + STF + PRF);   // [512][7] u64

    // ---- transpose per-feature weights into smem ----
    #pragma unroll
    for (int m = 0; m < 7; m++) {
        const float* gw = prm.p[12 + m] + (size_t)f * (Hv*Hv);
        float* wm = wT + m*Hv*WST;
        for (int i = tid; i < Hv*Hv; i += NTHREADS) {
            int k = i >> 6, j = i & 63;
            wm[j*WST + k] = gw[i];
        }
    }
    // params: [0..7]=U_j,U_i,U_f,U_o,U_c,U_last,U_time,Dw ; [8..18]=Wci..b_d
    // (grid-stride loop so ALL 19*64 params are loaded)
    for (int i = tid; i < 19*Hv; i += NTHREADS) {
        int m = i >> 6, j = i & 63;
        pUV[m*Hv + j] = (m < 8 ? prm.p[4 + m] : prm.p[19 + (m - 8)])[f*Hv + j];
    }
    for (int i = tid; i < STF; i += NTHREADS) sH[i] = 0.0f;
    __syncthreads();

    float hreg[4] = {0.f,0.f,0.f,0.f};
    float creg[4] = {0.f,0.f,0.f,0.f};

    // phase-1 matrix for this mhalf: mh=0 -> W_decomp (m=6) on c; mh=1 -> W_d (m=5) on h
    const float* wP1 = wT + (mh ? 5 : 6)*Hv*WST + jcol*WST;
    const float* sP1 = mh ? sH : sC;
    u64* myslot = red + tid*7;
    u64* pslot  = red + (tid ^ 256)*7;

    for (int s = 0; s < Tv; s++) {
        const int t_x   = dir ? (Tv-1-s) : s;
        const int t_tm  = dir ? (s == 0 ? 0 : Tv - s) : s;
        const int t_out = dir ? (Tv-1-s) : s;

        // ===== phase 1 matmul: this thread's single matrix, 8 batches =====
        u64 a1[4] = {0ULL,0ULL,0ULL,0ULL};
        #pragma unroll 4
        for (int k0 = 0; k0 < Hv; k0 += 4) {
            float4 wv = *(const float4*)(wP1 + k0);
            const float wva[4] = {wv.x, wv.y, wv.z, wv.w};
            #pragma unroll
            for (int kk = 0; kk < 4; kk++) {
                int k = k0 + kk;
                ulonglong2 s0 = *(const ulonglong2*)(sP1 + k*BST + b0);
                ulonglong2 s1 = *(const ulonglong2*)(sP1 + k*BST + b0 + 4);
                u64 w2 = pk2(wva[kk]);
                fma2(a1[0], s0.x, w2); fma2(a1[1], s0.y, w2);
                fma2(a1[2], s1.x, w2); fma2(a1[3], s1.y, w2);
            }
        }
        // exchange: give partner the half it needs (final sums, no adds)
        if (mh == 0) { myslot[0] = a1[2]; myslot[1] = a1[3]; }  // aD for batches 4..7
        else         { myslot[0] = a1[0]; myslot[1] = a1[1]; }  // aF for batches 0..3
        __syncthreads();
        u64 aDl0, aDl1, aFl0, aFl1;
        if (mh == 0) { aDl0 = a1[0];    aDl1 = a1[1];    aFl0 = pslot[0]; aFl1 = pslot[1]; }
        else         { aDl0 = pslot[0]; aDl1 = pslot[1]; aFl0 = a1[2];    aFl1 = a1[3];    }

        // ===== phase-1 elementwise for this thread's 4 batches (bsel..+3) =====
        float c2r[4], ltr[4], tma[4], fwa[4];
        {
            const float4 lv4 = *(const float4*)&g_lT[(s   *Fv + f)*Bv + bsel];
            const float4 tm4 = *(const float4*)&g_Tm[(t_tm*Fv + f)*Bv + bsel];
            const float4 fw4 = *(const float4*)&g_fw[ s*Bv + bsel];
            const float lva[4] = {lv4.x, lv4.y, lv4.z, lv4.w};
            tma[0]=tm4.x; tma[1]=tm4.y; tma[2]=tm4.z; tma[3]=tm4.w;
            fwa[0]=fw4.x; fwa[1]=fw4.y; fwa[2]=fw4.z; fwa[3]=fw4.w;
            float2 d0 = up2(aDl0), d1 = up2(aDl1);
            float2 g0 = up2(aFl0), g1 = up2(aFl1);
            const float a1a[4] = {d0.x, d0.y, d1.x, d1.y};
            const float a2a[4] = {g0.x, g0.y, g1.x, g1.y};
            const float Dw = pUV[7*Hv + jcol];
            const float Ul = pUV[5*Hv + jcol];
            const float bd = pUV[18*Hv + jcol];
            const float bl = pUV[16*Hv + jcol];
            float h2r[4];
            #pragma unroll
            for (int bb = 0; bb < 4; bb++) {
                float dst  = tanf_(a1a[bb]);
                float fd1  = sigf(fwa[bb]*Dw + a2a[bb] + bd);
                float ddec = dst * (tma[bb] * fd1);
                c2r[bb] = ddec + (creg[bb] - dst + ddec);
                ltr[bb] = eluf(lva[bb]*Ul + bl);
                h2r[bb] = hreg[bb] + ltr[bb];
            }
            *(float4*)(sH2 + jcol*BST + bsel) = make_float4(h2r[0],h2r[1],h2r[2],h2r[3]);
        }
        __syncthreads();

        // ===== phase-2 matmul: 3 matrices for this mhalf, 8 batches, full k =====
        // mh=0: m = 0,1,2 (W_j,W_i,W_f) ; mh=1: m = 3,4,5 (W_o,W_c,W_d)
        u64 acc[3][4];
        #pragma unroll
        for (int mm = 0; mm < 3; mm++)
            #pragma unroll
            for (int p = 0; p < 4; p++) acc[mm][p] = 0ULL;
        {
            const float* wp0 = wT + (mh*3 + 0)*Hv*WST + jcol*WST;
            const float* wp1 = wT + (mh*3 + 1)*Hv*WST + jcol*WST;
            const float* wp2 = wT + (mh*3 + 2)*Hv*WST + jcol*WST;
            #pragma unroll 2
            for (int k0 = 0; k0 < Hv; k0 += 4) {
                float4 wv0 = *(const float4*)(wp0 + k0);
                float4 wv1 = *(const float4*)(wp1 + k0);
                float4 wv2 = *(const float4*)(wp2 + k0);
                #pragma unroll
                for (int kk = 0; kk < 4; kk++) {
                    int k = k0 + kk;
                    ulonglong2 au0 = *(const ulonglong2*)(sH2 + k*BST + b0);
                    ulonglong2 au1 = *(const ulonglong2*)(sH2 + k*BST + b0 + 4);
                    u64 w20 = pk2(((const float*)&wv0)[kk]);
                    u64 w21 = pk2(((const float*)&wv1)[kk]);
                    u64 w22 = pk2(((const float*)&wv2)[kk]);
                    fma2(acc[0][0], au0.x, w20); fma2(acc[0][1], au0.y, w20);
                    fma2(acc[0][2], au1.x, w20); fma2(acc[0][3], au1.y, w20);
                    fma2(acc[1][0], au0.x, w21); fma2(acc[1][1], au0.y, w21);
                    fma2(acc[1][2], au1.x, w21); fma2(acc[1][3], au1.y, w21);
                    fma2(acc[2][0], au0.x, w22); fma2(acc[2][1], au0.y, w22);
                    fma2(acc[2][2], au1.x, w22); fma2(acc[2][3], au1.y, w22);
                }
            }
        }
        // exchange: store the batch-half the partner finishes (final sums)
        if (mh == 0) {
            #pragma unroll
            for (int mm = 0; mm < 3; mm++) {       // batches 4..7 of W_j/i/f
                myslot[2*mm]   = acc[mm][2];
                myslot[2*mm+1] = acc[mm][3];
            }
        } else {
            #pragma unroll
            for (int mm = 0; mm < 3; mm++) {       // batches 0..3 of W_o/c/d
                myslot[2*mm]   = acc[mm][0];
                myslot[2*mm+1] = acc[mm][1];
            }
        }
        __syncthreads();

        // ===== phase-2 elementwise for this thread's 4 batches =====
        {
            float am[6][4];
            if (mh == 0) {
                #pragma unroll
                for (int mm = 0; mm < 3; mm++) {
                    float2 lo = up2(acc[mm][0]), hi = up2(acc[mm][1]);
                    am[mm][0]=lo.x; am[mm][1]=lo.y; am[mm][2]=hi.x; am[mm][3]=hi.y;
                    float2 pl = up2(pslot[2*mm]), ph = up2(pslot[2*mm+1]);
                    am[3+mm][0]=pl.x; am[3+mm][1]=pl.y; am[3+mm][2]=ph.x; am[3+mm][3]=ph.y;
                }
            } else {
                #pragma unroll
                for (int mm = 0; mm < 3; mm++) {
                    float2 pl = up2(pslot[2*mm]), ph = up2(pslot[2*mm+1]);
                    am[mm][0]=pl.x; am[mm][1]=pl.y; am[mm][2]=ph.x; am[mm][3]=ph.y;
                    float2 lo = up2(acc[mm][2]), hi = up2(acc[mm][3]);
                    am[3+mm][0]=lo.x; am[3+mm][1]=lo.y; am[3+mm][2]=hi.x; am[3+mm][3]=hi.y;
                }
            }
            const float4 xv4 = *(const float4*)&g_xT [(t_x *Fv + f)*Bv + bsel];
            const float4 st4 = *(const float4*)&g_sTm[(t_tm*Fv + f)*Bv + bsel];
            const float xva[4] = {xv4.x, xv4.y, xv4.z, xv4.w};
            const float sta[4] = {st4.x, st4.y, st4.z, st4.w};
            const float Uj  = pUV[0*Hv + jcol];
            const float Ui  = pUV[1*Hv + jcol];
            const float Uf  = pUV[2*Hv + jcol];
            const float Uo  = pUV[3*Hv + jcol];
            const float Uc  = pUV[4*Hv + jcol];
            const float Ut  = pUV[6*Hv + jcol];
            const float Dw  = pUV[7*Hv + jcol];
            const float Wci = pUV[8*Hv + jcol];
            const float Wcf = pUV[9*Hv + jcol];
            const float Wco = pUV[10*Hv + jcol];
            const float bj  = pUV[11*Hv + jcol];
            const float bi  = pUV[12*Hv + jcol];
            const float bf  = pUV[13*Hv + jcol];
            const float bo  = pUV[14*Hv + jcol];
            const float bc  = pUV[15*Hv + jcol];
            const float bt  = pUV[17*Hv + jcol];
            const float bd  = pUV[18*Hv + jcol];
            #pragma unroll
            for (int bb = 0; bb < 4; bb++) {
                float c2 = c2r[bb];
                float lt = ltr[bb];
                float jg  = tanf_(am[0][bb] + xva[bb]*Uj + bj);
                float tg  = sigf(xva[bb]*Ut + sta[bb] + bt);
                float fd2 = sigf(fwa[bb]*Dw + am[5][bb] + bd);
                float ig  = sigf(xva[bb]*Ui + am[1][bb] + c2*Wci + bi*fd2);
                float fg  = sigf(xva[bb]*Uf + am[2][bb] + c2*Wcf + bf + jg);
                float fn  = fg*tma[bb] + (1.0f - fg)*fd2;
                float cg  = tanf_(xva[bb]*Uc + am[4][bb] + bc);
                float ct  = (fn + tg)*c2 + ig*jg*tg*cg;
                float og  = sigf(xva[bb]*Uo + am[3][bb] + tg + lt + ct*Wco + bo);
                float hn  = og * tanf_(ct + lt);
                hreg[bb] = hn;
                creg[bb] = ct;
                out[((size_t)(t_out*Bv + bsel + bb)*Fv + f)*(2*Hv) + dir*Hv + jcol] = hn;
            }
        }
        *(float4*)(sH + jcol*BST + bsel) = make_float4(hreg[0],hreg[1],hreg[2],hreg[3]);
        *(float4*)(sC + jcol*BST + bsel) = make_float4(creg[0],creg[1],creg[2],creg[3]);
        __syncthreads();
    }
}

// ---------------------------------------------------------------------------
// Launch
// ---------------------------------------------------------------------------
extern "C" void kernel_launch(void* const* d_in, const int* in_sizes, int n_in,
                              void* d_out, int out_size) {
    KParams prm;
    for (int i = 0; i < 30; i++) prm.p[i] = (const float*)d_in[i];

    cudaFuncSetAttribute(tlstm_kernel,
                         cudaFuncAttributeMaxDynamicSharedMemorySize,
                         SMEM_FLOATS * (int)sizeof(float));

    prologue_kernel<<<Bv*Tv, Fv>>>(prm);
    tlstm_kernel<<<dim3(Fv, 2), NTHREADS, SMEM_FLOATS * sizeof(float)>>>(
        prm, (float*)d_out);
}

// round 10
// speedup vs baseline: 1.1208x; 1.1208x over previous
#include <cuda_runtime.h>
#include <math.h>

// Problem dims (fixed by the reference)
#define Bv 32
#define Tv 128
#define Fv 64
#define Hv 64
#define BST 36           // state row stride [j][b]: conflict-free STS.128 (36 % 32 == 4)
#define WST 68           // transposed weight row stride [j][k]: conflict-free LDS.128
#define NTHREADS 256

typedef unsigned long long u64;

// ---------------------------------------------------------------------------
// Scratch (allocation-free): transposed inputs + precomputed time terms
// ---------------------------------------------------------------------------
__device__ float g_xT[Tv*Fv*Bv];   // x   -> [t][f][b]
__device__ float g_lT[Tv*Fv*Bv];   // l   -> [t][f][b]
__device__ float g_Tm[Tv*Fv*Bv];   // 1/log(t+e)
__device__ float g_sTm[Tv*Fv*Bv];  // sigmoid(Tm)
__device__ float g_fw[Tv*Bv];      // sum_f exp(-0.5*freq[b,t,f])

struct KParams { const float* p[30]; };

// ---------------------------------------------------------------------------
// Prologue: transpose + time precompute + cross-feature freq reduction
// ---------------------------------------------------------------------------
__global__ void prologue_kernel(KParams prm) {
    int b  = blockIdx.x >> 7;          // / Tv
    int t  = blockIdx.x & (Tv - 1);
    int fi = threadIdx.x;

    const float* inputs = prm.p[0];
    const float* times  = prm.p[1];
    const float* lastv  = prm.p[2];
    const float* freqs  = prm.p[3];

    int gin  = (b*Tv + t)*Fv + fi;     // [B,T,F]
    int gout = (t*Fv + fi)*Bv + b;     // [T,F,B]

    g_xT[gout] = inputs[gin];
    g_lT[gout] = lastv[gin];
    float tv = times[gin];
    float tm = 1.0f / logf(tv + 2.718281828459045f);
    g_Tm[gout]  = tm;
    g_sTm[gout] = 1.0f / (1.0f + expf(-tm));

    float e = expf(-0.5f * freqs[gin]);
    #pragma unroll
    for (int off = 16; off > 0; off >>= 1)
        e += __shfl_down_sync(0xffffffffu, e, off);
    __shared__ float red[2];
    if ((threadIdx.x & 31) == 0) red[threadIdx.x >> 5] = e;
    __syncthreads();
    if (threadIdx.x == 0) g_fw[t*Bv + b] = red[0] + red[1];
}

// ---------------------------------------------------------------------------
// Packed f32x2 helpers
// ---------------------------------------------------------------------------
__device__ __forceinline__ u64 pk2(float x) {
    u64 r; asm("mov.b64 %0, {%1, %1};" : "=l"(r) : "f"(x)); return r;
}
__device__ __forceinline__ void fma2(u64& d, u64 a, u64 b) {
    asm("fma.rn.f32x2 %0, %1, %2, %0;" : "+l"(d) : "l"(a), "l"(b));
}
__device__ __forceinline__ float2 up2(u64 v) {
    float2 r; asm("mov.b64 {%0, %1}, %2;" : "=f"(r.x), "=f"(r.y) : "l"(v)); return r;
}

// ---------------------------------------------------------------------------
// Fast-but-accurate activations (identical numerics to all prior rounds)
// ---------------------------------------------------------------------------
__device__ __forceinline__ float sigf(float x) {
    return __fdividef(1.0f, 1.0f + __expf(-x));
}
__device__ __forceinline__ float tanf_(float x) {
    float e = __expf(-2.0f * fabsf(x));
    float r = __fdividef(1.0f - e, 1.0f + e);
    return copysignf(r, x);
}
__device__ __forceinline__ float eluf(float x) {
    return x > 0.0f ? x : (__expf(x) - 1.0f);
}

// ---------------------------------------------------------------------------
// Main kernel: one CTA per (feature, direction), 256 threads (8 warps).
// Warp w: b-group g = w>>1 (8 batches b0 = 8g), j-half = w&1.
// Thread owns output column jcol = (w&1)*32 + lane for its 8 batches.
// R10 deltas vs R6 (no arithmetic change):
//   - all per-step gmem loads hoisted above phase-1 (L2 latency covered)
//   - phase-1 k-loop fully unrolled, phase-2 unroll 4 (deeper LDS pipelining)
// ---------------------------------------------------------------------------
#define SMEM_FLOATS (7*Hv*WST + 3*Hv*BST)   // 37376 floats = 146 KB

__global__ __launch_bounds__(NTHREADS)
void tlstm_kernel(KParams prm, float* __restrict__ out) {
    const int f    = blockIdx.x;
    const int dir  = blockIdx.y;
    const int tid  = threadIdx.x;
    const int w    = tid >> 5;
    const int lane = tid & 31;
    const int b0   = (w >> 1) * 8;
    const int jcol = (w & 1) * 32 + lane;

    extern __shared__ float sm[];
    float* wT  = sm;                    // [7][Hv*WST] : wT[m][j*WST + k]
    float* sH  = sm + 7*Hv*WST;         // [Hv][BST]   : h[hidden][b]
    float* sC  = sH + Hv*BST;
    float* sH2 = sC + Hv*BST;

    // ---- transpose per-feature weights into smem ----
    #pragma unroll
    for (int m = 0; m < 7; m++) {
        const float* gw = prm.p[12 + m] + (size_t)f * (Hv*Hv);
        float* wm = wT + m*Hv*WST;
        for (int i = tid; i < Hv*Hv; i += NTHREADS) {
            int k = i >> 6, j = i & 63;
            wm[j*WST + k] = gw[i];
        }
    }
    for (int i = tid; i < 3*Hv*BST; i += NTHREADS) sH[i] = 0.0f;

    // ---- hoist per-column params (loop-invariant) into registers ----
    const float Uj  = prm.p[4 ][f*Hv + jcol];
    const float Ui  = prm.p[5 ][f*Hv + jcol];
    const float Uf  = prm.p[6 ][f*Hv + jcol];
    const float Uo  = prm.p[7 ][f*Hv + jcol];
    const float Uc  = prm.p[8 ][f*Hv + jcol];
    const float Ul  = prm.p[9 ][f*Hv + jcol];
    const float Ut  = prm.p[10][f*Hv + jcol];
    const float Dw  = prm.p[11][f*Hv + jcol];
    const float Wci = prm.p[19][f*Hv + jcol];
    const float Wcf = prm.p[20][f*Hv + jcol];
    const float Wco = prm.p[21][f*Hv + jcol];
    const float bj  = prm.p[22][f*Hv + jcol];
    const float bi  = prm.p[23][f*Hv + jcol];
    const float bf  = prm.p[24][f*Hv + jcol];
    const float bo  = prm.p[25][f*Hv + jcol];
    const float bc  = prm.p[26][f*Hv + jcol];
    const float bl  = prm.p[27][f*Hv + jcol];
    const float bt  = prm.p[28][f*Hv + jcol];
    const float bd  = prm.p[29][f*Hv + jcol];
    __syncthreads();

    float hreg[8] = {0.f,0.f,0.f,0.f,0.f,0.f,0.f,0.f};
    float creg[8] = {0.f,0.f,0.f,0.f,0.f,0.f,0.f,0.f};

    const float* wDd  = wT + 5*Hv*WST + jcol*WST;   // W_d row for this column
    const float* wDec = wT + 6*Hv*WST + jcol*WST;   // W_decomp row

    for (int s = 0; s < Tv; s++) {
        const int t_x   = dir ? (Tv-1-s) : s;
        const int t_tm  = dir ? (s == 0 ? 0 : Tv - s) : s;
        const int t_out = dir ? (Tv-1-s) : s;

        // ===== hoisted gmem loads for this step (L2 latency hidden by MM1) ====
        const float4 lvA = *(const float4*)&g_lT [(s   *Fv + f)*Bv + b0];
        const float4 lvB = *(const float4*)&g_lT [(s   *Fv + f)*Bv + b0 + 4];
        const float4 tmA = *(const float4*)&g_Tm [(t_tm*Fv + f)*Bv + b0];
        const float4 tmB = *(const float4*)&g_Tm [(t_tm*Fv + f)*Bv + b0 + 4];
        const float4 fwA = *(const float4*)&g_fw [ s*Bv + b0];
        const float4 fwB = *(const float4*)&g_fw [ s*Bv + b0 + 4];
        const float4 xvA = *(const float4*)&g_xT [(t_x *Fv + f)*Bv + b0];
        const float4 xvB = *(const float4*)&g_xT [(t_x *Fv + f)*Bv + b0 + 4];
        const float4 stA = *(const float4*)&g_sTm[(t_tm*Fv + f)*Bv + b0];
        const float4 stB = *(const float4*)&g_sTm[(t_tm*Fv + f)*Bv + b0 + 4];

        // ===== phase 1: c @ W_decomp, h @ W_d (column jcol, 8 batches) =====
        u64 aD[4] = {0ULL,0ULL,0ULL,0ULL};   // c@W_decomp, pairs (b0,b1)..(b6,b7)
        u64 aF[4] = {0ULL,0ULL,0ULL,0ULL};   // h@W_d
        #pragma unroll
        for (int k0 = 0; k0 < Hv; k0 += 4) {
            float4 wde = *(const float4*)(wDec + k0);
            float4 wdd = *(const float4*)(wDd  + k0);
            const float wdea[4] = {wde.x, wde.y, wde.z, wde.w};
            const float wdda[4] = {wdd.x, wdd.y, wdd.z, wdd.w};
            #pragma unroll
            for (int kk = 0; kk < 4; kk++) {
                int k = k0 + kk;
                ulonglong2 cu0 = *(const ulonglong2*)(sC + k*BST + b0);
                ulonglong2 cu1 = *(const ulonglong2*)(sC + k*BST + b0 + 4);
                ulonglong2 hu0 = *(const ulonglong2*)(sH + k*BST + b0);
                ulonglong2 hu1 = *(const ulonglong2*)(sH + k*BST + b0 + 4);
                u64 we2 = pk2(wdea[kk]);
                u64 wd2 = pk2(wdda[kk]);
                fma2(aD[0], cu0.x, we2); fma2(aD[1], cu0.y, we2);
                fma2(aD[2], cu1.x, we2); fma2(aD[3], cu1.y, we2);
                fma2(aF[0], hu0.x, wd2); fma2(aF[1], hu0.y, wd2);
                fma2(aF[2], hu1.x, wd2); fma2(aF[3], hu1.y, wd2);
            }
        }
        // phase-1 elementwise; keep c2/lt in regs
        float c2r[8], ltr[8], tma[8], fwa[8];
        {
            const float lva[8] = {lvA.x,lvA.y,lvA.z,lvA.w, lvB.x,lvB.y,lvB.z,lvB.w};
            tma[0]=tmA.x; tma[1]=tmA.y; tma[2]=tmA.z; tma[3]=tmA.w;
            tma[4]=tmB.x; tma[5]=tmB.y; tma[6]=tmB.z; tma[7]=tmB.w;
            fwa[0]=fwA.x; fwa[1]=fwA.y; fwa[2]=fwA.z; fwa[3]=fwA.w;
            fwa[4]=fwB.x; fwa[5]=fwB.y; fwa[6]=fwB.z; fwa[7]=fwB.w;
            float a1a[8], a2a[8];
            #pragma unroll
            for (int p = 0; p < 4; p++) {
                float2 d = up2(aD[p]); a1a[2*p] = d.x; a1a[2*p+1] = d.y;
                float2 g = up2(aF[p]); a2a[2*p] = g.x; a2a[2*p+1] = g.y;
            }
            float h2r[8];
            #pragma unroll
            for (int bb = 0; bb < 8; bb++) {
                float dst  = tanf_(a1a[bb]);
                float fd1  = sigf(fwa[bb]*Dw + a2a[bb] + bd);
                float ddec = dst * (tma[bb] * fd1);
                c2r[bb] = ddec + (creg[bb] - dst + ddec);
                ltr[bb] = eluf(lva[bb]*Ul + bl);
                h2r[bb] = hreg[bb] + ltr[bb];
            }
            *(float4*)(sH2 + jcol*BST + b0)     = make_float4(h2r[0],h2r[1],h2r[2],h2r[3]);
            *(float4*)(sH2 + jcol*BST + b0 + 4) = make_float4(h2r[4],h2r[5],h2r[6],h2r[7]);
        }
        __syncthreads();

        // ===== phase 2: h2 @ {W_j, W_i, W_f, W_o, W_c, W_d} =====
        u64 acc[6][4];
        #pragma unroll
        for (int m = 0; m < 6; m++)
            #pragma unroll
            for (int p = 0; p < 4; p++) acc[m][p] = 0ULL;

        #pragma unroll 4
        for (int k0 = 0; k0 < Hv; k0 += 4) {
            float4 wv[6];
            #pragma unroll
            for (int m = 0; m < 6; m++)
                wv[m] = *(const float4*)(wT + m*Hv*WST + jcol*WST + k0);
            #pragma unroll
            for (int kk = 0; kk < 4; kk++) {
                ulonglong2 au0 = *(const ulonglong2*)(sH2 + (k0+kk)*BST + b0);
                ulonglong2 au1 = *(const ulonglong2*)(sH2 + (k0+kk)*BST + b0 + 4);
                #pragma unroll
                for (int m = 0; m < 6; m++) {
                    u64 w2 = pk2(((const float*)&wv[m])[kk]);
                    fma2(acc[m][0], au0.x, w2);
                    fma2(acc[m][1], au0.y, w2);
                    fma2(acc[m][2], au1.x, w2);
                    fma2(acc[m][3], au1.y, w2);
                }
            }
        }

        // phase-2 elementwise: gates, state update, output
        {
            const float xva[8] = {xvA.x,xvA.y,xvA.z,xvA.w, xvB.x,xvB.y,xvB.z,xvB.w};
            const float sta[8] = {stA.x,stA.y,stA.z,stA.w, stB.x,stB.y,stB.z,stB.w};
            float am[6][8];
            #pragma unroll
            for (int m = 0; m < 6; m++)
                #pragma unroll
                for (int p = 0; p < 4; p++) {
                    float2 v = up2(acc[m][p]);
                    am[m][2*p] = v.x; am[m][2*p+1] = v.y;
                }
            #pragma unroll
            for (int bb = 0; bb < 8; bb++) {
                float c2 = c2r[bb];
                float lt = ltr[bb];
                float jg  = tanf_(am[0][bb] + xva[bb]*Uj + bj);
                float tg  = sigf(xva[bb]*Ut + sta[bb] + bt);
                float fd2 = sigf(fwa[bb]*Dw + am[5][bb] + bd);
                float ig  = sigf(xva[bb]*Ui + am[1][bb] + c2*Wci + bi*fd2);
                float fg  = sigf(xva[bb]*Uf + am[2][bb] + c2*Wcf + bf + jg);
                float fn  = fg*tma[bb] + (1.0f - fg)*fd2;
                float cg  = tanf_(xva[bb]*Uc + am[4][bb] + bc);
                float ct  = (fn + tg)*c2 + ig*jg*tg*cg;
                float og  = sigf(xva[bb]*Uo + am[3][bb] + tg + lt + ct*Wco + bo);
                float hn  = og * tanf_(ct + lt);
                hreg[bb] = hn;
                creg[bb] = ct;
                out[((size_t)(t_out*Bv + b0 + bb)*Fv + f)*(2*Hv) + dir*Hv + jcol] = hn;
            }
        }
        *(float4*)(sH + jcol*BST + b0)     = make_float4(hreg[0],hreg[1],hreg[2],hreg[3]);
        *(float4*)(sH + jcol*BST + b0 + 4) = make_float4(hreg[4],hreg[5],hreg[6],hreg[7]);
        *(float4*)(sC + jcol*BST + b0)     = make_float4(creg[0],creg[1],creg[2],creg[3]);
        *(float4*)(sC + jcol*BST + b0 + 4) = make_float4(creg[4],creg[5],creg[6],creg[7]);
        __syncthreads();
    }
}

// ---------------------------------------------------------------------------
// Launch
// ---------------------------------------------------------------------------
extern "C" void kernel_launch(void* const* d_in, const int* in_sizes, int n_in,
                              void* d_out, int out_size) {
    KParams prm;
    for (int i = 0; i < 30; i++) prm.p[i] = (const float*)d_in[i];

    cudaFuncSetAttribute(tlstm_kernel,
                         cudaFuncAttributeMaxDynamicSharedMemorySize,
                         SMEM_FLOATS * (int)sizeof(float));

    prologue_kernel<<<Bv*Tv, Fv>>>(prm);
    tlstm_kernel<<<dim3(Fv, 2), NTHREADS, SMEM_FLOATS * sizeof(float)>>>(
        prm, (float*)d_out);
}

// round 11
// speedup vs baseline: 1.3150x; 1.1732x over previous
#include <cuda_runtime.h>
#include <math.h>

// Problem dims (fixed by the reference)
#define Bv 32
#define Tv 128
#define Fv 64
#define Hv 64
#define BST 36           // state row stride [j][b]: conflict-free STS.128 (36 % 32 == 4)
#define WST 68           // transposed weight row stride [j][k]: conflict-free LDS.128
#define NTHREADS 256
#define STB (Hv*BST)     // one state plane: 2304 floats

typedef unsigned long long u64;

// ---------------------------------------------------------------------------
// Scratch (allocation-free): transposed inputs + precomputed time terms
// ---------------------------------------------------------------------------
__device__ float g_xT[Tv*Fv*Bv];   // x   -> [t][f][b]
__device__ float g_lT[Tv*Fv*Bv];   // l   -> [t][f][b]
__device__ float g_Tm[Tv*Fv*Bv];   // 1/log(t+e)
__device__ float g_sTm[Tv*Fv*Bv];  // sigmoid(Tm)
__device__ float g_fw[Tv*Bv];      // sum_f exp(-0.5*freq[b,t,f])

struct KParams { const float* p[30]; };

// ---------------------------------------------------------------------------
// Prologue: transpose + time precompute + cross-feature freq reduction
// ---------------------------------------------------------------------------
__global__ void prologue_kernel(KParams prm) {
    int b  = blockIdx.x >> 7;          // / Tv
    int t  = blockIdx.x & (Tv - 1);
    int fi = threadIdx.x;

    const float* inputs = prm.p[0];
    const float* times  = prm.p[1];
    const float* lastv  = prm.p[2];
    const float* freqs  = prm.p[3];

    int gin  = (b*Tv + t)*Fv + fi;     // [B,T,F]
    int gout = (t*Fv + fi)*Bv + b;     // [T,F,B]

    g_xT[gout] = inputs[gin];
    g_lT[gout] = lastv[gin];
    float tv = times[gin];
    float tm = 1.0f / logf(tv + 2.718281828459045f);
    g_Tm[gout]  = tm;
    g_sTm[gout] = 1.0f / (1.0f + expf(-tm));

    float e = expf(-0.5f * freqs[gin]);
    #pragma unroll
    for (int off = 16; off > 0; off >>= 1)
        e += __shfl_down_sync(0xffffffffu, e, off);
    __shared__ float red[2];
    if ((threadIdx.x & 31) == 0) red[threadIdx.x >> 5] = e;
    __syncthreads();
    if (threadIdx.x == 0) g_fw[t*Bv + b] = red[0] + red[1];
}

// ---------------------------------------------------------------------------
// Packed f32x2 helpers
// ---------------------------------------------------------------------------
__device__ __forceinline__ u64 pk2(float x) {
    u64 r; asm("mov.b64 %0, {%1, %1};" : "=l"(r) : "f"(x)); return r;
}
__device__ __forceinline__ void fma2(u64& d, u64 a, u64 b) {
    asm("fma.rn.f32x2 %0, %1, %2, %0;" : "+l"(d) : "l"(a), "l"(b));
}
__device__ __forceinline__ float2 up2(u64 v) {
    float2 r; asm("mov.b64 {%0, %1}, %2;" : "=f"(r.x), "=f"(r.y) : "l"(v)); return r;
}

// ---------------------------------------------------------------------------
// Fast-but-accurate activations (identical numerics to all prior rounds)
// ---------------------------------------------------------------------------
__device__ __forceinline__ float sigf(float x) {
    return __fdividef(1.0f, 1.0f + __expf(-x));
}
__device__ __forceinline__ float tanf_(float x) {
    float e = __expf(-2.0f * fabsf(x));
    float r = __fdividef(1.0f - e, 1.0f + e);
    return copysignf(r, x);
}
__device__ __forceinline__ float eluf(float x) {
    return x > 0.0f ? x : (__expf(x) - 1.0f);
}

// ---------------------------------------------------------------------------
// Main kernel: one CTA per (feature, direction), 256 threads (8 warps).
// Warp w: b-group g = w>>1 (8 batches b0 = 8g), j-half = w&1.
// R11: SINGLE fused matmul block per step (c@W_decomp, h@W_d, h2@{6 W}),
// enabled by computing h2[s] = h_new + lt[s] at the END of step s-1
// (lt depends only on inputs). Double-buffered state -> ONE barrier/step.
// Per-matrix k-accumulation order unchanged -> bitwise-identical results.
// ---------------------------------------------------------------------------
#define SMEM_FLOATS (7*Hv*WST + 6*STB)   // 30464 + 13824 = 44288 floats = 173 KB

__global__ __launch_bounds__(NTHREADS)
void tlstm_kernel(KParams prm, float* __restrict__ out) {
    const int f    = blockIdx.x;
    const int dir  = blockIdx.y;
    const int tid  = threadIdx.x;
    const int w    = tid >> 5;
    const int lane = tid & 31;
    const int b0   = (w >> 1) * 8;
    const int jcol = (w & 1) * 32 + lane;

    extern __shared__ float sm[];
    float* wT = sm;                    // [7][Hv*WST] : wT[m][j*WST + k]
    float* sB = sm + 7*Hv*WST;         // [2 parities][h | c | h2], each Hv*BST

    // ---- transpose per-feature weights into smem ----
    #pragma unroll
    for (int m = 0; m < 7; m++) {
        const float* gw = prm.p[12 + m] + (size_t)f * (Hv*Hv);
        float* wm = wT + m*Hv*WST;
        for (int i = tid; i < Hv*Hv; i += NTHREADS) {
            int k = i >> 6, j = i & 63;
            wm[j*WST + k] = gw[i];
        }
    }
    // zero h and c of buffer 0
    for (int i = tid; i < 2*STB; i += NTHREADS) sB[i] = 0.0f;

    // ---- hoist per-column params (loop-invariant) into registers ----
    const float Uj  = prm.p[4 ][f*Hv + jcol];
    const float Ui  = prm.p[5 ][f*Hv + jcol];
    const float Uf  = prm.p[6 ][f*Hv + jcol];
    const float Uo  = prm.p[7 ][f*Hv + jcol];
    const float Uc  = prm.p[8 ][f*Hv + jcol];
    const float Ul  = prm.p[9 ][f*Hv + jcol];
    const float Ut  = prm.p[10][f*Hv + jcol];
    const float Dw  = prm.p[11][f*Hv + jcol];
    const float Wci = prm.p[19][f*Hv + jcol];
    const float Wcf = prm.p[20][f*Hv + jcol];
    const float Wco = prm.p[21][f*Hv + jcol];
    const float bj  = prm.p[22][f*Hv + jcol];
    const float bi  = prm.p[23][f*Hv + jcol];
    const float bf  = prm.p[24][f*Hv + jcol];
    const float bo  = prm.p[25][f*Hv + jcol];
    const float bc  = prm.p[26][f*Hv + jcol];
    const float bl  = prm.p[27][f*Hv + jcol];
    const float bt  = prm.p[28][f*Hv + jcol];
    const float bd  = prm.p[29][f*Hv + jcol];

    // ---- initial lt[0] and h2[0] = 0 + lt[0] into buffer 0 ----
    float ltr[8];
    {
        const float4 lA = *(const float4*)&g_lT[(0*Fv + f)*Bv + b0];
        const float4 lB = *(const float4*)&g_lT[(0*Fv + f)*Bv + b0 + 4];
        const float lva[8] = {lA.x,lA.y,lA.z,lA.w, lB.x,lB.y,lB.z,lB.w};
        #pragma unroll
        for (int bb = 0; bb < 8; bb++) ltr[bb] = eluf(lva[bb]*Ul + bl);
        *(float4*)(sB + 2*STB + jcol*BST + b0)     = make_float4(ltr[0],ltr[1],ltr[2],ltr[3]);
        *(float4*)(sB + 2*STB + jcol*BST + b0 + 4) = make_float4(ltr[4],ltr[5],ltr[6],ltr[7]);
    }
    __syncthreads();

    float creg[8] = {0.f,0.f,0.f,0.f,0.f,0.f,0.f,0.f};

    const float* wDd  = wT + 5*Hv*WST + jcol*WST;   // W_d row for this column
    const float* wDec = wT + 6*Hv*WST + jcol*WST;   // W_decomp row

    for (int s = 0; s < Tv; s++) {
        const int p  = s & 1;
        const int np = p ^ 1;
        const float* cH  = sB + p*3*STB;
        const float* cC  = cH + STB;
        const float* cH2 = cC + STB;
        float* nH  = sB + np*3*STB;
        float* nC  = nH + STB;
        float* nH2 = nC + STB;

        const int t_x   = dir ? (Tv-1-s) : s;
        const int t_tm  = dir ? (s == 0 ? 0 : Tv - s) : s;
        const int t_out = dir ? (Tv-1-s) : s;
        const int lidx  = (s + 1 < Tv) ? s + 1 : Tv - 1;   // l for NEXT step

        // ===== hoisted gmem loads (latency covered by the fused matmul) =====
        const float4 tmA = *(const float4*)&g_Tm [(t_tm*Fv + f)*Bv + b0];
        const float4 tmB = *(const float4*)&g_Tm [(t_tm*Fv + f)*Bv + b0 + 4];
        const float4 fwA = *(const float4*)&g_fw [ s*Bv + b0];
        const float4 fwB = *(const float4*)&g_fw [ s*Bv + b0 + 4];
        const float4 xvA = *(const float4*)&g_xT [(t_x *Fv + f)*Bv + b0];
        const float4 xvB = *(const float4*)&g_xT [(t_x *Fv + f)*Bv + b0 + 4];
        const float4 stA = *(const float4*)&g_sTm[(t_tm*Fv + f)*Bv + b0];
        const float4 stB = *(const float4*)&g_sTm[(t_tm*Fv + f)*Bv + b0 + 4];
        const float4 lnA = *(const float4*)&g_lT [(lidx*Fv + f)*Bv + b0];
        const float4 lnB = *(const float4*)&g_lT [(lidx*Fv + f)*Bv + b0 + 4];

        // ===== fused matmul: c@W_decomp, h@W_d, h2@{W_j,W_i,W_f,W_o,W_c,W_d}
        u64 aD[4] = {0ULL,0ULL,0ULL,0ULL};
        u64 aF[4] = {0ULL,0ULL,0ULL,0ULL};
        u64 acc[6][4];
        #pragma unroll
        for (int m = 0; m < 6; m++)
            #pragma unroll
            for (int q = 0; q < 4; q++) acc[m][q] = 0ULL;

        #pragma unroll 4
        for (int k0 = 0; k0 < Hv; k0 += 4) {
            float4 wv[6];
            #pragma unroll
            for (int m = 0; m < 6; m++)
                wv[m] = *(const float4*)(wT + m*Hv*WST + jcol*WST + k0);
            float4 wde = *(const float4*)(wDec + k0);
            float4 wdd = *(const float4*)(wDd  + k0);
            #pragma unroll
            for (int kk = 0; kk < 4; kk++) {
                int k = k0 + kk;
                ulonglong2 cu0 = *(const ulonglong2*)(cC  + k*BST + b0);
                ulonglong2 cu1 = *(const ulonglong2*)(cC  + k*BST + b0 + 4);
                ulonglong2 hu0 = *(const ulonglong2*)(cH  + k*BST + b0);
                ulonglong2 hu1 = *(const ulonglong2*)(cH  + k*BST + b0 + 4);
                ulonglong2 au0 = *(const ulonglong2*)(cH2 + k*BST + b0);
                ulonglong2 au1 = *(const ulonglong2*)(cH2 + k*BST + b0 + 4);
                u64 we2 = pk2(((const float*)&wde)[kk]);
                u64 wd2 = pk2(((const float*)&wdd)[kk]);
                fma2(aD[0], cu0.x, we2); fma2(aD[1], cu0.y, we2);
                fma2(aD[2], cu1.x, we2); fma2(aD[3], cu1.y, we2);
                fma2(aF[0], hu0.x, wd2); fma2(aF[1], hu0.y, wd2);
                fma2(aF[2], hu1.x, wd2); fma2(aF[3], hu1.y, wd2);
                #pragma unroll
                for (int m = 0; m < 6; m++) {
                    u64 w2 = pk2(((const float*)&wv[m])[kk]);
                    fma2(acc[m][0], au0.x, w2);
                    fma2(acc[m][1], au0.y, w2);
                    fma2(acc[m][2], au1.x, w2);
                    fma2(acc[m][3], au1.y, w2);
                }
            }
        }

        // ===== elementwise (phase-1 + phase-2 fused, formulas unchanged) ====
        {
            float tma[8], fwa[8];
            tma[0]=tmA.x; tma[1]=tmA.y; tma[2]=tmA.z; tma[3]=tmA.w;
            tma[4]=tmB.x; tma[5]=tmB.y; tma[6]=tmB.z; tma[7]=tmB.w;
            fwa[0]=fwA.x; fwa[1]=fwA.y; fwa[2]=fwA.z; fwa[3]=fwA.w;
            fwa[4]=fwB.x; fwa[5]=fwB.y; fwa[6]=fwB.z; fwa[7]=fwB.w;
            float a1a[8], a2a[8];
            #pragma unroll
            for (int q = 0; q < 4; q++) {
                float2 d = up2(aD[q]); a1a[2*q] = d.x; a1a[2*q+1] = d.y;
                float2 g = up2(aF[q]); a2a[2*q] = g.x; a2a[2*q+1] = g.y;
            }
            float c2r[8];
            #pragma unroll
            for (int bb = 0; bb < 8; bb++) {
                float dst  = tanf_(a1a[bb]);
                float fd1  = sigf(fwa[bb]*Dw + a2a[bb] + bd);
                float ddec = dst * (tma[bb] * fd1);
                c2r[bb] = ddec + (creg[bb] - dst + ddec);
            }

            const float xva[8] = {xvA.x,xvA.y,xvA.z,xvA.w, xvB.x,xvB.y,xvB.z,xvB.w};
            const float sta[8] = {stA.x,stA.y,stA.z,stA.w, stB.x,stB.y,stB.z,stB.w};
            const float lna[8] = {lnA.x,lnA.y,lnA.z,lnA.w, lnB.x,lnB.y,lnB.z,lnB.w};
            float am[6][8];
            #pragma unroll
            for (int m = 0; m < 6; m++)
                #pragma unroll
                for (int q = 0; q < 4; q++) {
                    float2 v = up2(acc[m][q]);
                    am[m][2*q] = v.x; am[m][2*q+1] = v.y;
                }
            float hna[8], ltn[8];
            #pragma unroll
            for (int bb = 0; bb < 8; bb++) {
                float c2 = c2r[bb];
                float lt = ltr[bb];
                float jg  = tanf_(am[0][bb] + xva[bb]*Uj + bj);
                float tg  = sigf(xva[bb]*Ut + sta[bb] + bt);
                float fd2 = sigf(fwa[bb]*Dw + am[5][bb] + bd);
                float ig  = sigf(xva[bb]*Ui + am[1][bb] + c2*Wci + bi*fd2);
                float fg  = sigf(xva[bb]*Uf + am[2][bb] + c2*Wcf + bf + jg);
                float fn  = fg*tma[bb] + (1.0f - fg)*fd2;
                float cg  = tanf_(xva[bb]*Uc + am[4][bb] + bc);
                float ct  = (fn + tg)*c2 + ig*jg*tg*cg;
                float og  = sigf(xva[bb]*Uo + am[3][bb] + tg + lt + ct*Wco + bo);
                float hn  = og * tanf_(ct + lt);
                creg[bb] = ct;
                hna[bb]  = hn;
                ltn[bb]  = eluf(lna[bb]*Ul + bl);     // lt for step s+1
                out[((size_t)(t_out*Bv + b0 + bb)*Fv + f)*(2*Hv) + dir*Hv + jcol] = hn;
            }
            // store next-step state: h, c, h2 = h + lt[s+1]
            *(float4*)(nH  + jcol*BST + b0)     = make_float4(hna[0],hna[1],hna[2],hna[3]);
            *(float4*)(nH  + jcol*BST + b0 + 4) = make_float4(hna[4],hna[5],hna[6],hna[7]);
            *(float4*)(nC  + jcol*BST + b0)     = make_float4(creg[0],creg[1],creg[2],creg[3]);
            *(float4*)(nC  + jcol*BST + b0 + 4) = make_float4(creg[4],creg[5],creg[6],creg[7]);
            *(float4*)(nH2 + jcol*BST + b0)     = make_float4(hna[0]+ltn[0],hna[1]+ltn[1],
                                                              hna[2]+ltn[2],hna[3]+ltn[3]);
            *(float4*)(nH2 + jcol*BST + b0 + 4) = make_float4(hna[4]+ltn[4],hna[5]+ltn[5],
                                                              hna[6]+ltn[6],hna[7]+ltn[7]);
            #pragma unroll
            for (int bb = 0; bb < 8; bb++) ltr[bb] = ltn[bb];
        }
        __syncthreads();
    }
}

// ---------------------------------------------------------------------------
// Launch
// ---------------------------------------------------------------------------
extern "C" void kernel_launch(void* const* d_in, const int* in_sizes, int n_in,
                              void* d_out, int out_size) {
    KParams prm;
    for (int i = 0; i < 30; i++) prm.p[i] = (const float*)d_in[i];

    cudaFuncSetAttribute(tlstm_kernel,
                         cudaFuncAttributeMaxDynamicSharedMemorySize,
                         SMEM_FLOATS * (int)sizeof(float));

    prologue_kernel<<<Bv*Tv, Fv>>>(prm);
    tlstm_kernel<<<dim3(Fv, 2), NTHREADS, SMEM_FLOATS * sizeof(float)>>>(
        prm, (float*)d_out);
}